// round 16
// baseline (speedup 1.0000x reference)
#include <cuda_runtime.h>
#include <cuda_bf16.h>
#include <mma.h>
#include <cstdint>

using namespace nvcuda;

typedef unsigned long long u64;

#define Bsz    256
#define Ssz    512
#define Tsz    20
#define Esz    25
#define Hsz    128
#define SKIPsz 64
#define Gsz    512            // 4*H
#define NROWS  (Bsz*Ssz)      // 131072 ; row r = t*256 + b (t-major)

// ---------------- scratch (static device globals; no allocation) ----------
__device__ float g_xpool[(size_t)NROWS * Esz];        // [t*256+b][25]
__device__ float g_mask [(size_t)NROWS];              // [t*256+b]
__device__ float g_P    [(size_t)2 * NROWS * Gsz];    // [dir][t*256+b][512]  (NO bias)
__device__ float g_out  [(size_t)NROWS * 256];        // [b*512+t][256] (f|b)
__device__ float g_hf   [(size_t)Bsz * Hsz];          // final fwd h
__device__ float g_qwq  [(size_t)Bsz * Hsz];          // h_fwd@Wq + bq
__device__ float g_energy[(size_t)NROWS];             // [b*512+t]

// ---------------- f32x2 helpers -------------------------------------------
__device__ __forceinline__ u64 pk(float a, float b) {
    u64 r;
    asm("mov.b64 %0, {%1, %2};" : "=l"(r) : "r"(__float_as_uint(a)), "r"(__float_as_uint(b)));
    return r;
}
__device__ __forceinline__ void upk(u64 v, float& a, float& b) {
    unsigned lo, hi;
    asm("mov.b64 {%0, %1}, %2;" : "=r"(lo), "=r"(hi) : "l"(v));
    a = __uint_as_float(lo); b = __uint_as_float(hi);
}
__device__ __forceinline__ void fma2(u64& d, u64 a, u64 b) {
    asm("fma.rn.f32x2 %0, %1, %2, %0;" : "+l"(d) : "l"(a), "l"(b));
}
__device__ __forceinline__ float hadd(u64 v) {
    float a, b; upk(v, a, b); return a + b;
}

// ---------------- math helpers (tanh.approx fast path) ---------------------
__device__ __forceinline__ float tanhapx(float x) {
    float y; asm("tanh.approx.f32 %0, %1;" : "=f"(y) : "f"(x)); return y;
}
__device__ __forceinline__ float sigapx(float x) {
    return fmaf(tanhapx(0.5f * x), 0.5f, 0.5f);
}
__device__ __forceinline__ uint32_t smem_u32(const void* p) {
    uint32_t a;
    asm("{ .reg .u64 t; cvta.to.shared.u64 t, %1; cvt.u32.u64 %0, t; }" : "=r"(a) : "l"(p));
    return a;
}
__device__ __forceinline__ void st_rem_b16(uint32_t addr, __nv_bfloat16 v) {
    unsigned short s = *(unsigned short*)&v;
    asm volatile("st.shared::cluster.b16 [%0], %1;" :: "r"(addr), "h"(s) : "memory");
}

// ================= K1: embedding mean-pool + step mask (split x2) ==========
__global__ void k_embed(const int* __restrict__ tags, const float* __restrict__ emb, int base) {
    int g    = base + blockIdx.x * 8 + (threadIdx.x >> 5);
    int lane = threadIdx.x & 31;
    int b = g >> 9, s = g & 511;
    const int* tg = tags + (size_t)g * Tsz;
    float acc = 0.f; int cnt = 0; int first = 0;
    #pragma unroll
    for (int i = 0; i < Tsz; i++) {
        int tv = __ldg(tg + i);
        if (i == 0) first = tv;
        if (tv != 0) {
            cnt++;
            if (lane < Esz) acc += __ldg(emb + (size_t)tv * Esz + lane);
        }
    }
    int r = s * Bsz + b;
    if (lane < Esz) g_xpool[(size_t)r * Esz + lane] = acc / (cnt ? (float)cnt : 1.f);
    if (lane == 0)  g_mask[r] = (first != 0) ? 1.f : 0.f;
}

// ================= K2: prologue GEMM via wmma (bf16 2-split, HMMA) =========
#define PSM_AHI 0
#define PSM_ALO (256 * 96 * 2)
#define PSM_BHI (2 * 256 * 96 * 2)
#define PSM_BLO (2 * 256 * 96 * 2 + 96 * 256 * 2)
#define PSM_TOTAL (2 * 256 * 96 * 2 + 2 * 96 * 256 * 2)   // 196608 B
__global__ __launch_bounds__(512, 1)
void k_progemm(const float* __restrict__ skips,
               const float* __restrict__ Kf, const float* __restrict__ Skf,
               const float* __restrict__ Kb, const float* __restrict__ Skb) {
    extern __shared__ __align__(16) char psm[];
    __nv_bfloat16* Ahi = (__nv_bfloat16*)(psm + PSM_AHI);   // [256][96]
    __nv_bfloat16* Alo = (__nv_bfloat16*)(psm + PSM_ALO);
    __nv_bfloat16* Bhi = (__nv_bfloat16*)(psm + PSM_BHI);   // [96][256]
    __nv_bfloat16* Blo = (__nv_bfloat16*)(psm + PSM_BLO);

    int tid = threadIdx.x, d = blockIdx.y, bg = blockIdx.x;
    int w = tid >> 5;
    const float* Kw = d ? Kb : Kf;
    const float* Sw = d ? Skb : Skf;
    float* Pd = g_P + (size_t)d * NROWS * Gsz;

    #pragma unroll 1
    for (int half = 0; half < 2; half++) {
        __syncthreads();
        #pragma unroll 1
        for (int e = tid; e < 96 * 256; e += 512) {
            int k = e >> 8, n = e & 255;
            int col = half * 256 + n;
            float v = 0.f;
            if (k < Esz)      v = __ldg(Kw + (size_t)k * Gsz + col);
            else if (k < 89)  v = __ldg(Sw + (size_t)(k - Esz) * Gsz + col);
            __nv_bfloat16 h = __float2bfloat16(v);
            __nv_bfloat16 l = __float2bfloat16(v - __bfloat162float(h));
            Bhi[e] = h; Blo[e] = l;
        }
        #pragma unroll 1
        for (int mt = 0; mt < 8; mt++) {
            int r0 = (bg * 8 + mt) * 256;
            __syncthreads();
            #pragma unroll 1
            for (int e = tid; e < 256 * 96; e += 512) {
                int m = e / 96, k = e - m * 96;
                int r = r0 + m;
                int tt = r >> 8, bb2 = r & 255;
                float v = 0.f;
                if (k < Esz)      v = g_xpool[(size_t)r * Esz + k];
                else if (k < 89)  v = __ldg(skips + ((size_t)(bb2 << 9) + tt) * SKIPsz + (k - Esz));
                __nv_bfloat16 h = __float2bfloat16(v);
                __nv_bfloat16 l = __float2bfloat16(v - __bfloat162float(h));
                Ahi[e] = h; Alo[e] = l;
            }
            __syncthreads();
            const __nv_bfloat16* Aw_hi = Ahi + w * 16 * 96;
            const __nv_bfloat16* Aw_lo = Alo + w * 16 * 96;
            #pragma unroll 1
            for (int grp = 0; grp < 2; grp++) {
                wmma::fragment<wmma::accumulator, 16, 16, 16, float> acc[8];
                #pragma unroll
                for (int nf = 0; nf < 8; nf++) wmma::fill_fragment(acc[nf], 0.f);
                #pragma unroll 1
                for (int k = 0; k < 6; k++) {
                    wmma::fragment<wmma::matrix_a, 16, 16, 16, __nv_bfloat16, wmma::row_major> ah, al;
                    wmma::load_matrix_sync(ah, Aw_hi + k * 16, 96);
                    wmma::load_matrix_sync(al, Aw_lo + k * 16, 96);
                    #pragma unroll
                    for (int nf = 0; nf < 8; nf++) {
                        int n0 = (grp * 8 + nf) * 16;
                        wmma::fragment<wmma::matrix_b, 16, 16, 16, __nv_bfloat16, wmma::row_major> bh, bl;
                        wmma::load_matrix_sync(bh, Bhi + k * 16 * 256 + n0, 256);
                        wmma::load_matrix_sync(bl, Blo + k * 16 * 256 + n0, 256);
                        wmma::mma_sync(acc[nf], ah, bh, acc[nf]);
                        wmma::mma_sync(acc[nf], al, bh, acc[nf]);
                        wmma::mma_sync(acc[nf], ah, bl, acc[nf]);
                    }
                }
                #pragma unroll
                for (int nf = 0; nf < 8; nf++) {
                    int n0 = half * 256 + (grp * 8 + nf) * 16;
                    wmma::store_matrix_sync(Pd + (size_t)(r0 + w * 16) * Gsz + n0,
                                            acc[nf], Gsz, wmma::mem_row_major);
                }
            }
        }
    }
}

// ================= K3: LSTM via tensor cores + CTA-pair cluster ============
// Same structure as R15 (proven correct). Change: 6 independent accumulator
// chains per warp (by product type) instead of 2x 24-deep chains; Rlo
// fragments loaded from smem per step (register budget).
#define LSTM_SMEM (131072 + 16384 + 16384)
__global__ __launch_bounds__(256, 1) __cluster_dims__(2, 1, 1)
void k_lstm(const float* __restrict__ Rf, const float* __restrict__ Rb,
            const float* __restrict__ bf, const float* __restrict__ bb) {
    extern __shared__ __align__(16) char smraw[];
    __nv_bfloat16* Rhi = (__nv_bfloat16*)smraw;                 // [128][256]
    __nv_bfloat16* Rlo = Rhi + 128 * 256;
    __nv_bfloat16* hB  = (__nv_bfloat16*)(smraw + 131072);      // [buf][hl][16][128]
    float* z_sm = (float*)(smraw + 131072 + 16384);             // [16][256]

    int tau = threadIdx.x, d = blockIdx.y;
    int bgrp = blockIdx.x >> 1;
    int r = blockIdx.x & 1;
    int w = tau >> 5;
    const float* R  = d ? Rb : Rf;
    const float* bw = d ? bb : bf;
    int b0 = bgrp * 8;

    // stage R hi/lo: local col n = gate*64 + u ; global col = gate*128 + r*64 + u
    #pragma unroll 1
    for (int e = tau; e < 128 * 256; e += 256) {
        int k = e >> 8, n = e & 255;
        int gcol = (n >> 6) * 128 + r * 64 + (n & 63);
        float v = __ldg(R + (size_t)k * Gsz + gcol);
        __nv_bfloat16 h = __float2bfloat16(v);
        Rhi[e] = h;
        Rlo[e] = __float2bfloat16(v - __bfloat162float(h));
    }
    for (int e = tau; e < 2 * 2 * 16 * 128; e += 256) hB[e] = __float2bfloat16(0.f);
    __syncthreads();

    // persistent B-hi fragments only: warp w owns n-tiles 2w, 2w+1
    wmma::fragment<wmma::matrix_b, 16, 16, 16, __nv_bfloat16, wmma::row_major> FBh[8][2];
    #pragma unroll
    for (int kt = 0; kt < 8; kt++) {
        #pragma unroll
        for (int j = 0; j < 2; j++)
            wmma::load_matrix_sync(FBh[kt][j], Rhi + kt * 16 * 256 + (2 * w + j) * 16, 256);
    }

    int u = tau & 63, bl0 = tau >> 6, bl1 = 4 + (tau >> 6);
    int ug = r * 64 + u;
    float bi = __ldg(bw + ug),        bft = __ldg(bw + 128 + ug);
    float bg = __ldg(bw + 256 + ug),  bo  = __ldg(bw + 384 + ug);
    const float* Pd = g_P + (size_t)d * NROWS * Gsz;
    int t = d ? (Ssz - 1) : 0, dt = d ? -1 : 1;

    float pi0, pf0, pg0, po0, pi1, pf1, pg1, po1, m0, m1;
    {
        size_t ro0 = (size_t)(t * Bsz + b0 + bl0) * Gsz;
        size_t ro1 = (size_t)(t * Bsz + b0 + bl1) * Gsz;
        pi0 = Pd[ro0 + ug] + bi;       pf0 = Pd[ro0 + 128 + ug] + bft;
        pg0 = Pd[ro0 + 256 + ug] + bg; po0 = Pd[ro0 + 384 + ug] + bo;
        pi1 = Pd[ro1 + ug] + bi;       pf1 = Pd[ro1 + 128 + ug] + bft;
        pg1 = Pd[ro1 + 256 + ug] + bg; po1 = Pd[ro1 + 384 + ug] + bo;
        m0 = g_mask[t * Bsz + b0 + bl0];
        m1 = g_mask[t * Bsz + b0 + bl1];
    }
    float c0 = 0.f, c1 = 0.f, hp0 = 0.f, hp1 = 0.f;

    uint32_t hloc = smem_u32(hB);
    uint32_t hrem;
    {
        uint32_t peer = (uint32_t)(r ^ 1);
        asm("mapa.shared::cluster.u32 %0, %1, %2;" : "=r"(hrem) : "r"(hloc), "r"(peer));
    }

    asm volatile("barrier.cluster.arrive.aligned;" ::: "memory");
    asm volatile("barrier.cluster.wait.aligned;" ::: "memory");

    #pragma unroll 1
    for (int i = 0; i < Ssz; i++) {
        int cb = i & 1, nb2 = cb ^ 1;
        const __nv_bfloat16* Hhi = hB + (cb * 2 + 0) * 2048;
        const __nv_bfloat16* Hlo = hB + (cb * 2 + 1) * 2048;

        // 6 independent accumulate chains: {A=AhBh, B=AlBh, C=AhBl} x n-tile
        wmma::fragment<wmma::accumulator, 16, 16, 16, float> aA0, aB0, aC0, aA1, aB1, aC1;
        wmma::fill_fragment(aA0, 0.f); wmma::fill_fragment(aB0, 0.f); wmma::fill_fragment(aC0, 0.f);
        wmma::fill_fragment(aA1, 0.f); wmma::fill_fragment(aB1, 0.f); wmma::fill_fragment(aC1, 0.f);
        #pragma unroll
        for (int kt = 0; kt < 8; kt++) {
            wmma::fragment<wmma::matrix_a, 16, 16, 16, __nv_bfloat16, wmma::row_major> Ah, Al;
            wmma::load_matrix_sync(Ah, Hhi + kt * 16, 128);
            wmma::load_matrix_sync(Al, Hlo + kt * 16, 128);
            wmma::fragment<wmma::matrix_b, 16, 16, 16, __nv_bfloat16, wmma::row_major> Bl0, Bl1;
            wmma::load_matrix_sync(Bl0, Rlo + kt * 16 * 256 + (2 * w) * 16, 256);
            wmma::load_matrix_sync(Bl1, Rlo + kt * 16 * 256 + (2 * w + 1) * 16, 256);
            wmma::mma_sync(aA0, Ah, FBh[kt][0], aA0);
            wmma::mma_sync(aA1, Ah, FBh[kt][1], aA1);
            wmma::mma_sync(aB0, Al, FBh[kt][0], aB0);
            wmma::mma_sync(aB1, Al, FBh[kt][1], aB1);
            wmma::mma_sync(aC0, Ah, Bl0, aC0);
            wmma::mma_sync(aC1, Ah, Bl1, aC1);
        }
        #pragma unroll
        for (int e = 0; e < aA0.num_elements; e++) {
            aA0.x[e] += aB0.x[e] + aC0.x[e];
            aA1.x[e] += aB1.x[e] + aC1.x[e];
        }
        wmma::store_matrix_sync(z_sm + (2 * w) * 16, aA0, 256, wmma::mem_row_major);
        wmma::store_matrix_sync(z_sm + (2 * w + 1) * 16, aA1, 256, wmma::mem_row_major);

        // prefetch next-step P (+bias) and masks
        int tn = t + dt;
        float ni0 = 0.f, nf0 = 0.f, ng0 = 0.f, no0 = 0.f;
        float ni1 = 0.f, nf1 = 0.f, ng1 = 0.f, no1 = 0.f;
        float nm0 = 0.f, nm1 = 0.f;
        if (i < Ssz - 1) {
            size_t ro0 = (size_t)(tn * Bsz + b0 + bl0) * Gsz;
            size_t ro1 = (size_t)(tn * Bsz + b0 + bl1) * Gsz;
            ni0 = Pd[ro0 + ug] + bi;       nf0 = Pd[ro0 + 128 + ug] + bft;
            ng0 = Pd[ro0 + 256 + ug] + bg; no0 = Pd[ro0 + 384 + ug] + bo;
            ni1 = Pd[ro1 + ug] + bi;       nf1 = Pd[ro1 + 128 + ug] + bft;
            ng1 = Pd[ro1 + 256 + ug] + bg; no1 = Pd[ro1 + 384 + ug] + bo;
            nm0 = g_mask[tn * Bsz + b0 + bl0];
            nm1 = g_mask[tn * Bsz + b0 + bl1];
        }
        __syncthreads();

        float zi0 = z_sm[bl0 * 256 + u] + pi0;
        float zf0 = z_sm[bl0 * 256 + 64 + u] + pf0;
        float zg0 = z_sm[bl0 * 256 + 128 + u] + pg0;
        float zo0 = z_sm[bl0 * 256 + 192 + u] + po0;
        float zi1 = z_sm[bl1 * 256 + u] + pi1;
        float zf1 = z_sm[bl1 * 256 + 64 + u] + pf1;
        float zg1 = z_sm[bl1 * 256 + 128 + u] + pg1;
        float zo1 = z_sm[bl1 * 256 + 192 + u] + po1;

        float cn0 = sigapx(zf0) * c0 + sigapx(zi0) * tanhapx(zg0);
        float hn0 = sigapx(zo0) * tanhapx(cn0);
        float cn1 = sigapx(zf1) * c1 + sigapx(zi1) * tanhapx(zg1);
        float hn1 = sigapx(zo1) * tanhapx(cn1);
        bool mm0 = (m0 != 0.f), mm1 = (m1 != 0.f);
        float hv0 = mm0 ? hn0 : hp0; c0 = mm0 ? cn0 : c0;
        float hv1 = mm1 ? hn1 : hp1; c1 = mm1 ? cn1 : c1;
        hp0 = hv0; hp1 = hv1;

        __nv_bfloat16 hh0 = __float2bfloat16(hv0);
        __nv_bfloat16 hl0 = __float2bfloat16(hv0 - __bfloat162float(hh0));
        __nv_bfloat16 hh1 = __float2bfloat16(hv1);
        __nv_bfloat16 hl1 = __float2bfloat16(hv1 - __bfloat162float(hh1));
        int oh0 = (nb2 * 2 + 0) * 2048 + bl0 * 128 + ug;
        int ol0 = (nb2 * 2 + 1) * 2048 + bl0 * 128 + ug;
        int oh1 = (nb2 * 2 + 0) * 2048 + bl1 * 128 + ug;
        int ol1 = (nb2 * 2 + 1) * 2048 + bl1 * 128 + ug;
        hB[oh0] = hh0; hB[ol0] = hl0;
        hB[oh1] = hh1; hB[ol1] = hl1;
        st_rem_b16(hrem + oh0 * 2, hh0);
        st_rem_b16(hrem + ol0 * 2, hl0);
        st_rem_b16(hrem + oh1 * 2, hh1);
        st_rem_b16(hrem + ol1 * 2, hl1);

        g_out[(((size_t)(b0 + bl0) << 9) + t) * 256 + (d << 7) + ug] = hv0;
        g_out[(((size_t)(b0 + bl1) << 9) + t) * 256 + (d << 7) + ug] = hv1;
        if (d == 0 && i == Ssz - 1) {
            g_hf[(b0 + bl0) * Hsz + ug] = hv0;
            g_hf[(b0 + bl1) * Hsz + ug] = hv1;
        }

        asm volatile("barrier.cluster.arrive.aligned;" ::: "memory");
        asm volatile("barrier.cluster.wait.aligned;" ::: "memory");

        pi0 = ni0; pf0 = nf0; pg0 = ng0; po0 = no0;
        pi1 = ni1; pf1 = nf1; pg1 = ng1; po1 = no1;
        m0 = nm0; m1 = nm1; t = tn;
    }
}

// ================= K4: queries = h_fwd @ Wq + bq ============================
__global__ void k_qw(const float* __restrict__ Wq, const float* __restrict__ bq) {
    __shared__ float hf[Hsz];
    int b = blockIdx.x, i = threadIdx.x;
    hf[i] = g_hf[b * Hsz + i];
    __syncthreads();
    float acc = __ldg(bq + i);
    #pragma unroll 8
    for (int k = 0; k < Hsz; k++) acc = fmaf(hf[k], __ldg(Wq + k * Hsz + i), acc);
    g_qwq[b * Hsz + i] = acc;
}

// ================= K5: keys GEMM + tanh + energy (R3 + tanh.approx) ========
__global__ __launch_bounds__(512, 1)
void k_keys(const float* __restrict__ Wk, const float* __restrict__ bk,
            const float* __restrict__ We, const float* __restrict__ be) {
    __shared__ __align__(16) u64 row2[4][128];
    __shared__ float qb[128], bks[128];
    __shared__ float partial[3][4][128];
    __shared__ float part2[4][4];

    int tid = threadIdx.x;
    int jc = tid & 127, qtr = tid >> 7;
    int blk = blockIdx.x;
    int b = blk >> 2;
    int r0 = blk * 128;

    u64 wq[32];
    #pragma unroll
    for (int i = 0; i < 32; i++) {
        int k0 = qtr * 64 + 2 * i;
        wq[i] = pk(__ldg(Wk + (size_t)k0 * Hsz + jc), __ldg(Wk + (size_t)(k0 + 1) * Hsz + jc));
    }
    if (tid < 128) { qb[tid] = g_qwq[b * Hsz + tid]; bks[tid] = __ldg(bk + tid); }
    float Wej = __ldg(We + jc);
    float bev = __ldg(be);
    __syncthreads();

    #pragma unroll 1
    for (int rr = 0; rr < 128; rr += 4) {
        {
            int ro = tid >> 7, p = tid & 127;
            const float2 v = *(const float2*)(g_out + (size_t)(r0 + rr + ro) * 256 + 2 * p);
            row2[ro][p] = pk(v.x, v.y);
        }
        __syncthreads();

        u64 a0 = pk(0.f, 0.f), a1 = a0, a2 = a0, a3 = a0;
        #pragma unroll
        for (int it = 0; it < 16; it++) {
            int p = qtr * 32 + 2 * it;
            u64 w0 = wq[2 * it], w1 = wq[2 * it + 1];
            ulonglong2 r_0 = *(const ulonglong2*)&row2[0][p];
            ulonglong2 r_1 = *(const ulonglong2*)&row2[1][p];
            ulonglong2 r_2 = *(const ulonglong2*)&row2[2][p];
            ulonglong2 r_3 = *(const ulonglong2*)&row2[3][p];
            fma2(a0, r_0.x, w0); fma2(a0, r_0.y, w1);
            fma2(a1, r_1.x, w0); fma2(a1, r_1.y, w1);
            fma2(a2, r_2.x, w0); fma2(a2, r_2.y, w1);
            fma2(a3, r_3.x, w0); fma2(a3, r_3.y, w1);
        }
        float acc[4] = { hadd(a0), hadd(a1), hadd(a2), hadd(a3) };
        if (qtr > 0) {
            #pragma unroll
            for (int ro = 0; ro < 4; ro++) partial[qtr - 1][ro][jc] = acc[ro];
        }
        __syncthreads();
        if (qtr == 0) {
            #pragma unroll
            for (int ro = 0; ro < 4; ro++) {
                float z = acc[ro] + partial[0][ro][jc] + partial[1][ro][jc] + partial[2][ro][jc]
                        + bks[jc] + qb[jc];
                float v = Wej * tanhapx(z);
                #pragma unroll
                for (int o = 16; o > 0; o >>= 1) v += __shfl_down_sync(0xffffffffu, v, o);
                if ((jc & 31) == 0) part2[ro][jc >> 5] = v;
            }
        }
        __syncthreads();
        if (tid < 4) {
            float e = part2[tid][0] + part2[tid][1] + part2[tid][2] + part2[tid][3] + bev;
            int r2 = r0 + rr + tid;
            int tt = r2 & 511;
            float m = g_mask[tt * Bsz + b];
            g_energy[r2] = e - (1.f - m) * 1e9f;
        }
        __syncthreads();
    }
}

// ================= K6: softmax over t + context =============================
__global__ __launch_bounds__(256, 1)
void k_softctx(float* __restrict__ out) {
    __shared__ float wsm[512];
    __shared__ float red[256];
    int b = blockIdx.x, tid = threadIdx.x;
    float e0 = g_energy[(size_t)b * 512 + tid];
    float e1 = g_energy[(size_t)b * 512 + 256 + tid];
    red[tid] = fmaxf(e0, e1);
    __syncthreads();
    #pragma unroll
    for (int o = 128; o > 0; o >>= 1) {
        if (tid < o) red[tid] = fmaxf(red[tid], red[tid + o]);
        __syncthreads();
    }
    float mx = red[0];
    __syncthreads();
    float x0 = __expf(e0 - mx), x1 = __expf(e1 - mx);
    wsm[tid] = x0; wsm[256 + tid] = x1;
    red[tid] = x0 + x1;
    __syncthreads();
    #pragma unroll
    for (int o = 128; o > 0; o >>= 1) {
        if (tid < o) red[tid] += red[tid + o];
        __syncthreads();
    }
    float inv = __fdividef(1.f, red[0]);

    const float* ob = g_out + (size_t)b * 512 * 256;
    float acc = 0.f;
    #pragma unroll 4
    for (int t = 0; t < 512; t++)
        acc = fmaf(wsm[t], __ldg(ob + (size_t)t * 256 + tid), acc);
    out[(size_t)b * 256 + tid] = acc * inv;
}

// ================= launch ===================================================
extern "C" void kernel_launch(void* const* d_in, const int* in_sizes, int n_in,
                              void* d_out, int out_size) {
    const int*   tags  = (const int*)  d_in[0];
    const float* skips = (const float*)d_in[1];
    const float* emb   = (const float*)d_in[2];
    const float* Kf    = (const float*)d_in[3];
    const float* Rf    = (const float*)d_in[4];
    const float* Skf   = (const float*)d_in[5];
    const float* bf    = (const float*)d_in[6];
    const float* Kb    = (const float*)d_in[7];
    const float* Rb    = (const float*)d_in[8];
    const float* Skb   = (const float*)d_in[9];
    const float* bb    = (const float*)d_in[10];
    const float* Wk    = (const float*)d_in[11];
    const float* bk    = (const float*)d_in[12];
    const float* Wq    = (const float*)d_in[13];
    const float* bq    = (const float*)d_in[14];
    const float* We    = (const float*)d_in[15];
    const float* be    = (const float*)d_in[16];
    float* out = (float*)d_out;

    cudaFuncSetAttribute(k_lstm, cudaFuncAttributeMaxDynamicSharedMemorySize, LSTM_SMEM);
    cudaFuncSetAttribute(k_progemm, cudaFuncAttributeMaxDynamicSharedMemorySize, PSM_TOTAL);

    k_embed<<<NROWS / 16, 256>>>(tags, emb, 0);
    k_embed<<<NROWS / 16, 256>>>(tags, emb, NROWS / 2);
    k_progemm<<<dim3(64, 2), 512, PSM_TOTAL>>>(skips, Kf, Skf, Kb, Skb);
    k_lstm<<<dim3(64, 2), 256, LSTM_SMEM>>>(Rf, Rb, bf, bb);   // launch #4 -> ncu
    k_qw<<<Bsz, Hsz>>>(Wq, bq);
    k_keys<<<1024, 512>>>(Wk, bk, We, be);
    k_softctx<<<Bsz, 256>>>(out);
}

// round 17
// speedup vs baseline: 1.6436x; 1.6436x over previous
#include <cuda_runtime.h>
#include <cuda_bf16.h>
#include <mma.h>
#include <cstdint>

using namespace nvcuda;

typedef unsigned long long u64;

#define Bsz    256
#define Ssz    512
#define Tsz    20
#define Esz    25
#define Hsz    128
#define SKIPsz 64
#define Gsz    512            // 4*H
#define NROWS  (Bsz*Ssz)      // 131072 ; row r = t*256 + b (t-major)

// ---------------- scratch (static device globals; no allocation) ----------
__device__ float g_xpool[(size_t)NROWS * Esz];        // [t*256+b][25]
__device__ float g_mask [(size_t)NROWS];              // [t*256+b]
__device__ float g_P    [(size_t)2 * NROWS * Gsz];    // [dir][t*256+b][512]  (NO bias)
__device__ float g_out  [(size_t)NROWS * 256];        // [b*512+t][256] (f|b)
__device__ float g_hf   [(size_t)Bsz * Hsz];          // final fwd h
__device__ float g_energy[(size_t)NROWS];             // [b*512+t]

// ---------------- f32x2 helpers -------------------------------------------
__device__ __forceinline__ u64 pk(float a, float b) {
    u64 r;
    asm("mov.b64 %0, {%1, %2};" : "=l"(r) : "r"(__float_as_uint(a)), "r"(__float_as_uint(b)));
    return r;
}
__device__ __forceinline__ void upk(u64 v, float& a, float& b) {
    unsigned lo, hi;
    asm("mov.b64 {%0, %1}, %2;" : "=r"(lo), "=r"(hi) : "l"(v));
    a = __uint_as_float(lo); b = __uint_as_float(hi);
}
__device__ __forceinline__ void fma2(u64& d, u64 a, u64 b) {
    asm("fma.rn.f32x2 %0, %1, %2, %0;" : "+l"(d) : "l"(a), "l"(b));
}
__device__ __forceinline__ float hadd(u64 v) {
    float a, b; upk(v, a, b); return a + b;
}

// ---------------- math helpers (tanh.approx fast path) ---------------------
__device__ __forceinline__ float tanhapx(float x) {
    float y; asm("tanh.approx.f32 %0, %1;" : "=f"(y) : "f"(x)); return y;
}
__device__ __forceinline__ float sigapx(float x) {
    return fmaf(tanhapx(0.5f * x), 0.5f, 0.5f);
}

// ================= K1: embedding mean-pool + step mask =====================
__global__ void k_embed(const int* __restrict__ tags, const float* __restrict__ emb) {
    int g    = blockIdx.x * 8 + (threadIdx.x >> 5);
    int lane = threadIdx.x & 31;
    if (g >= NROWS) return;
    int b = g >> 9, s = g & 511;
    const int* tg = tags + (size_t)g * Tsz;
    float acc = 0.f; int cnt = 0; int first = 0;
    #pragma unroll
    for (int i = 0; i < Tsz; i++) {
        int tv = __ldg(tg + i);
        if (i == 0) first = tv;
        if (tv != 0) {
            cnt++;
            if (lane < Esz) acc += __ldg(emb + (size_t)tv * Esz + lane);
        }
    }
    int r = s * Bsz + b;
    if (lane < Esz) g_xpool[(size_t)r * Esz + lane] = acc / (cnt ? (float)cnt : 1.f);
    if (lane == 0)  g_mask[r] = (first != 0) ? 1.f : 0.f;
}

// ================= K2: prologue GEMM via wmma (bf16 2-split, HMMA) =========
#define PSM_AHI 0
#define PSM_ALO (256 * 96 * 2)
#define PSM_BHI (2 * 256 * 96 * 2)
#define PSM_BLO (2 * 256 * 96 * 2 + 96 * 256 * 2)
#define PSM_TOTAL (2 * 256 * 96 * 2 + 2 * 96 * 256 * 2)   // 196608 B
__global__ __launch_bounds__(512, 1)
void k_progemm(const float* __restrict__ skips,
               const float* __restrict__ Kf, const float* __restrict__ Skf,
               const float* __restrict__ Kb, const float* __restrict__ Skb) {
    extern __shared__ __align__(16) char psm[];
    __nv_bfloat16* Ahi = (__nv_bfloat16*)(psm + PSM_AHI);   // [256][96]
    __nv_bfloat16* Alo = (__nv_bfloat16*)(psm + PSM_ALO);
    __nv_bfloat16* Bhi = (__nv_bfloat16*)(psm + PSM_BHI);   // [96][256]
    __nv_bfloat16* Blo = (__nv_bfloat16*)(psm + PSM_BLO);

    int tid = threadIdx.x, d = blockIdx.y, bg = blockIdx.x;
    int w = tid >> 5;
    const float* Kw = d ? Kb : Kf;
    const float* Sw = d ? Skb : Skf;
    float* Pd = g_P + (size_t)d * NROWS * Gsz;

    #pragma unroll 1
    for (int half = 0; half < 2; half++) {
        __syncthreads();
        #pragma unroll 1
        for (int e = tid; e < 96 * 256; e += 512) {
            int k = e >> 8, n = e & 255;
            int col = half * 256 + n;
            float v = 0.f;
            if (k < Esz)      v = __ldg(Kw + (size_t)k * Gsz + col);
            else if (k < 89)  v = __ldg(Sw + (size_t)(k - Esz) * Gsz + col);
            __nv_bfloat16 h = __float2bfloat16(v);
            __nv_bfloat16 l = __float2bfloat16(v - __bfloat162float(h));
            Bhi[e] = h; Blo[e] = l;
        }
        #pragma unroll 1
        for (int mt = 0; mt < 8; mt++) {
            int r0 = (bg * 8 + mt) * 256;
            __syncthreads();
            #pragma unroll 1
            for (int e = tid; e < 256 * 96; e += 512) {
                int m = e / 96, k = e - m * 96;
                int r = r0 + m;
                int tt = r >> 8, bb2 = r & 255;
                float v = 0.f;
                if (k < Esz)      v = g_xpool[(size_t)r * Esz + k];
                else if (k < 89)  v = __ldg(skips + ((size_t)(bb2 << 9) + tt) * SKIPsz + (k - Esz));
                __nv_bfloat16 h = __float2bfloat16(v);
                __nv_bfloat16 l = __float2bfloat16(v - __bfloat162float(h));
                Ahi[e] = h; Alo[e] = l;
            }
            __syncthreads();
            const __nv_bfloat16* Aw_hi = Ahi + w * 16 * 96;
            const __nv_bfloat16* Aw_lo = Alo + w * 16 * 96;
            #pragma unroll 1
            for (int grp = 0; grp < 2; grp++) {
                wmma::fragment<wmma::accumulator, 16, 16, 16, float> acc[8];
                #pragma unroll
                for (int nf = 0; nf < 8; nf++) wmma::fill_fragment(acc[nf], 0.f);
                #pragma unroll 1
                for (int k = 0; k < 6; k++) {
                    wmma::fragment<wmma::matrix_a, 16, 16, 16, __nv_bfloat16, wmma::row_major> ah, al;
                    wmma::load_matrix_sync(ah, Aw_hi + k * 16, 96);
                    wmma::load_matrix_sync(al, Aw_lo + k * 16, 96);
                    #pragma unroll
                    for (int nf = 0; nf < 8; nf++) {
                        int n0 = (grp * 8 + nf) * 16;
                        wmma::fragment<wmma::matrix_b, 16, 16, 16, __nv_bfloat16, wmma::row_major> bh, bl;
                        wmma::load_matrix_sync(bh, Bhi + k * 16 * 256 + n0, 256);
                        wmma::load_matrix_sync(bl, Blo + k * 16 * 256 + n0, 256);
                        wmma::mma_sync(acc[nf], ah, bh, acc[nf]);
                        wmma::mma_sync(acc[nf], al, bh, acc[nf]);
                        wmma::mma_sync(acc[nf], ah, bl, acc[nf]);
                    }
                }
                #pragma unroll
                for (int nf = 0; nf < 8; nf++) {
                    int n0 = half * 256 + (grp * 8 + nf) * 16;
                    wmma::store_matrix_sync(Pd + (size_t)(r0 + w * 16) * Gsz + n0,
                                            acc[nf], Gsz, wmma::mem_row_major);
                }
            }
        }
    }
}

// ================= K3: LSTM (256 thr, quad-lane gates, 1 barrier/step) ======
// R13-proven layout: thread u: unit q=u>>1, sel=u&1; cols colA=q+256*sel (i|g),
// colB=q+128+256*sel (f|o); z exchange via lane-pair shuffles; h2s double-buf.
#define LSTM_SMEM (65536 + 4096 + 8192)
__global__ __launch_bounds__(256, 1)
void k_lstm(const float* __restrict__ Rf, const float* __restrict__ Rb,
            const float* __restrict__ bf, const float* __restrict__ bb) {
    extern __shared__ __align__(16) char smraw[];
    ulonglong2* R4  = (ulonglong2*)smraw;                    // [w*512 + slot]
    u64*   h2s = (u64*)(smraw + 65536);                      // 2 bufs x [p*4+nb]
    float* msk = (float*)(smraw + 65536 + 4096);             // [t*4+nb]

    int u = threadIdx.x, d = blockIdx.y, bg = blockIdx.x;
    int q = u >> 1, sel = u & 1;
    int colA = q + 256 * sel;
    int colB = q + 128 + 256 * sel;
    const float* R = d ? Rb : Rf;
    const float* bw = d ? bb : bf;
    float bjA = __ldg(bw + colA);
    float bjB = __ldg(bw + colB);

    u64 RA[48], RB[48];
    #pragma unroll
    for (int p = 0; p < 48; p++) {
        RA[p] = pk(__ldg(R + (2 * p) * Gsz + colA), __ldg(R + (2 * p + 1) * Gsz + colA));
        RB[p] = pk(__ldg(R + (2 * p) * Gsz + colB), __ldg(R + (2 * p + 1) * Gsz + colB));
    }
    #pragma unroll 1
    for (int w = 0; w < 8; w++) {
        int r0 = 96 + 4 * w;
        ulonglong2 vA, vB;
        vA.x = pk(__ldg(R + (r0 + 0) * Gsz + colA), __ldg(R + (r0 + 1) * Gsz + colA));
        vA.y = pk(__ldg(R + (r0 + 2) * Gsz + colA), __ldg(R + (r0 + 3) * Gsz + colA));
        vB.x = pk(__ldg(R + (r0 + 0) * Gsz + colB), __ldg(R + (r0 + 1) * Gsz + colB));
        vB.y = pk(__ldg(R + (r0 + 2) * Gsz + colB), __ldg(R + (r0 + 3) * Gsz + colB));
        R4[w * 512 + u] = vA;
        R4[w * 512 + 256 + u] = vB;
    }
    h2s[u] = 0ULL;
    for (int e = u; e < 2048; e += 256)
        msk[e] = g_mask[(e >> 2) * Bsz + 4 * bg + (e & 3)];

    int nb0 = 2 * sel, nb1 = 2 * sel + 1;
    int myb0 = 4 * bg + nb0, myb1 = 4 * bg + nb1;
    float c0 = 0.f, c1 = 0.f, hp0 = 0.f, hp1 = 0.f;

    const float* Pd = g_P + (size_t)d * NROWS * Gsz;
    int t = d ? (Ssz - 1) : 0;
    int dt = d ? -1 : 1;
    float pvA0 = Pd[((size_t)(t * Bsz + 4 * bg + 0)) * Gsz + colA] + bjA;
    float pvA1 = Pd[((size_t)(t * Bsz + 4 * bg + 1)) * Gsz + colA] + bjA;
    float pvA2 = Pd[((size_t)(t * Bsz + 4 * bg + 2)) * Gsz + colA] + bjA;
    float pvA3 = Pd[((size_t)(t * Bsz + 4 * bg + 3)) * Gsz + colA] + bjA;
    float pvB0 = Pd[((size_t)(t * Bsz + 4 * bg + 0)) * Gsz + colB] + bjB;
    float pvB1 = Pd[((size_t)(t * Bsz + 4 * bg + 1)) * Gsz + colB] + bjB;
    float pvB2 = Pd[((size_t)(t * Bsz + 4 * bg + 2)) * Gsz + colB] + bjB;
    float pvB3 = Pd[((size_t)(t * Bsz + 4 * bg + 3)) * Gsz + colB] + bjB;
    __syncthreads();

    #pragma unroll 1
    for (int i = 0; i < Ssz; i++) {
        u64* hcur = h2s + (i & 1) * 256;
        u64* hnxt = h2s + ((i + 1) & 1) * 256;

        u64 aA0 = pk(pvA0, 0.f), aA1 = pk(pvA1, 0.f), aA2 = pk(pvA2, 0.f), aA3 = pk(pvA3, 0.f);
        u64 aB0 = pk(pvB0, 0.f), aB1 = pk(pvB1, 0.f), aB2 = pk(pvB2, 0.f), aB3 = pk(pvB3, 0.f);
        #pragma unroll
        for (int p = 0; p < 48; p++) {
            ulonglong2 ha = *(const ulonglong2*)&hcur[4 * p];
            ulonglong2 hb = *(const ulonglong2*)&hcur[4 * p + 2];
            fma2(aA0, ha.x, RA[p]); fma2(aA1, ha.y, RA[p]);
            fma2(aA2, hb.x, RA[p]); fma2(aA3, hb.y, RA[p]);
            fma2(aB0, ha.x, RB[p]); fma2(aB1, ha.y, RB[p]);
            fma2(aB2, hb.x, RB[p]); fma2(aB3, hb.y, RB[p]);
        }
        #pragma unroll
        for (int w = 0; w < 8; w++) {
            ulonglong2 rA = R4[w * 512 + u];
            ulonglong2 rB = R4[w * 512 + 256 + u];
            int p0 = 48 + 2 * w;
            ulonglong2 ha0 = *(const ulonglong2*)&hcur[4 * p0];
            ulonglong2 hb0 = *(const ulonglong2*)&hcur[4 * p0 + 2];
            ulonglong2 ha1 = *(const ulonglong2*)&hcur[4 * p0 + 4];
            ulonglong2 hb1 = *(const ulonglong2*)&hcur[4 * p0 + 6];
            fma2(aA0, ha0.x, rA.x); fma2(aA1, ha0.y, rA.x);
            fma2(aA2, hb0.x, rA.x); fma2(aA3, hb0.y, rA.x);
            fma2(aA0, ha1.x, rA.y); fma2(aA1, ha1.y, rA.y);
            fma2(aA2, hb1.x, rA.y); fma2(aA3, hb1.y, rA.y);
            fma2(aB0, ha0.x, rB.x); fma2(aB1, ha0.y, rB.x);
            fma2(aB2, hb0.x, rB.x); fma2(aB3, hb0.y, rB.x);
            fma2(aB0, ha1.x, rB.y); fma2(aB1, ha1.y, rB.y);
            fma2(aB2, hb1.x, rB.y); fma2(aB3, hb1.y, rB.y);
        }
        float vA0 = hadd(aA0), vA1 = hadd(aA1), vA2 = hadd(aA2), vA3 = hadd(aA3);
        float vB0 = hadd(aB0), vB1 = hadd(aB1), vB2 = hadd(aB2), vB3 = hadd(aB3);

        int tn = t + dt;
        float pnA0 = 0.f, pnA1 = 0.f, pnA2 = 0.f, pnA3 = 0.f;
        float pnB0 = 0.f, pnB1 = 0.f, pnB2 = 0.f, pnB3 = 0.f;
        if (i < Ssz - 1) {
            pnA0 = Pd[((size_t)(tn * Bsz + 4 * bg + 0)) * Gsz + colA] + bjA;
            pnA1 = Pd[((size_t)(tn * Bsz + 4 * bg + 1)) * Gsz + colA] + bjA;
            pnA2 = Pd[((size_t)(tn * Bsz + 4 * bg + 2)) * Gsz + colA] + bjA;
            pnA3 = Pd[((size_t)(tn * Bsz + 4 * bg + 3)) * Gsz + colA] + bjA;
            pnB0 = Pd[((size_t)(tn * Bsz + 4 * bg + 0)) * Gsz + colB] + bjB;
            pnB1 = Pd[((size_t)(tn * Bsz + 4 * bg + 1)) * Gsz + colB] + bjB;
            pnB2 = Pd[((size_t)(tn * Bsz + 4 * bg + 2)) * Gsz + colB] + bjB;
            pnB3 = Pd[((size_t)(tn * Bsz + 4 * bg + 3)) * Gsz + colB] + bjB;
        }

        float sA0 = __shfl_down_sync(0xffffffffu, vA0, 1);
        float sB0 = __shfl_down_sync(0xffffffffu, vB0, 1);
        float sA1 = __shfl_down_sync(0xffffffffu, vA1, 1);
        float sB1 = __shfl_down_sync(0xffffffffu, vB1, 1);
        float sA2 = __shfl_up_sync(0xffffffffu, vA2, 1);
        float sB2 = __shfl_up_sync(0xffffffffu, vB2, 1);
        float sA3 = __shfl_up_sync(0xffffffffu, vA3, 1);
        float sB3 = __shfl_up_sync(0xffffffffu, vB3, 1);

        float zi0 = sel ? sA2 : vA0, zf0 = sel ? sB2 : vB0;
        float zg0 = sel ? vA2 : sA0, zo0 = sel ? vB2 : sB0;
        float zi1 = sel ? sA3 : vA1, zf1 = sel ? sB3 : vB1;
        float zg1 = sel ? vA3 : sA1, zo1 = sel ? vB3 : sB1;

        float m0 = msk[t * 4 + nb0];
        float m1 = msk[t * 4 + nb1];
        float cn0 = sigapx(zf0) * c0 + sigapx(zi0) * tanhapx(zg0);
        float hn0 = sigapx(zo0) * tanhapx(cn0);
        float cn1 = sigapx(zf1) * c1 + sigapx(zi1) * tanhapx(zg1);
        float hn1 = sigapx(zo1) * tanhapx(cn1);
        bool mm0 = (m0 != 0.f), mm1 = (m1 != 0.f);
        float hv0 = mm0 ? hn0 : hp0; c0 = mm0 ? cn0 : c0;
        float hv1 = mm1 ? hn1 : hp1; c1 = mm1 ? cn1 : c1;
        hp0 = hv0; hp1 = hv1;

        g_out[(((size_t)myb0 << 9) + t) * 256 + (d << 7) + q] = hv0;
        g_out[(((size_t)myb1 << 9) + t) * 256 + (d << 7) + q] = hv1;
        if (d == 0 && i == Ssz - 1) {
            g_hf[myb0 * Hsz + q] = hv0;
            g_hf[myb1 * Hsz + q] = hv1;
        }

        float s0 = __shfl_down_sync(0xffffffffu, hv0, 2);
        float s1 = __shfl_down_sync(0xffffffffu, hv1, 2);
        if ((u & 2) == 0) {
            int p = q >> 1;
            hnxt[p * 4 + nb0] = pk(hv0, s0);
            hnxt[p * 4 + nb1] = pk(hv1, s1);
        }
        __syncthreads();
        pvA0 = pnA0; pvA1 = pnA1; pvA2 = pnA2; pvA3 = pnA3;
        pvB0 = pnB0; pvB1 = pnB1; pvB2 = pnB2; pvB3 = pnB3;
        t = tn;
    }
}

// ================= K4: keys GEMM + fused qw + tanh + energy =================
// R3-proven structure; qb = h_fwd@Wq + bq computed per block (fused k_qw).
__global__ __launch_bounds__(512, 1)
void k_keys(const float* __restrict__ Wk, const float* __restrict__ bk,
            const float* __restrict__ Wq, const float* __restrict__ bq,
            const float* __restrict__ We, const float* __restrict__ be) {
    __shared__ __align__(16) u64 row2[4][128];
    __shared__ float qb[128], bks[128], hfs[128];
    __shared__ float partial[3][4][128];
    __shared__ float part2[4][4];

    int tid = threadIdx.x;
    int jc = tid & 127, qtr = tid >> 7;
    int blk = blockIdx.x;
    int b = blk >> 2;
    int r0 = blk * 128;

    u64 wq[32];
    #pragma unroll
    for (int i = 0; i < 32; i++) {
        int k0 = qtr * 64 + 2 * i;
        wq[i] = pk(__ldg(Wk + (size_t)k0 * Hsz + jc), __ldg(Wk + (size_t)(k0 + 1) * Hsz + jc));
    }
    if (tid < 128) hfs[tid] = g_hf[b * Hsz + tid];
    __syncthreads();
    if (tid < 128) {
        float acc = __ldg(bq + tid);
        #pragma unroll 8
        for (int k = 0; k < Hsz; k++) acc = fmaf(hfs[k], __ldg(Wq + k * Hsz + tid), acc);
        qb[tid] = acc;
        bks[tid] = __ldg(bk + tid);
    }
    float Wej = __ldg(We + jc);
    float bev = __ldg(be);
    __syncthreads();

    #pragma unroll 1
    for (int rr = 0; rr < 128; rr += 4) {
        {
            int ro = tid >> 7, p = tid & 127;
            const float2 v = *(const float2*)(g_out + (size_t)(r0 + rr + ro) * 256 + 2 * p);
            row2[ro][p] = pk(v.x, v.y);
        }
        __syncthreads();

        u64 a0 = pk(0.f, 0.f), a1 = a0, a2 = a0, a3 = a0;
        #pragma unroll
        for (int it = 0; it < 16; it++) {
            int p = qtr * 32 + 2 * it;
            u64 w0 = wq[2 * it], w1 = wq[2 * it + 1];
            ulonglong2 r_0 = *(const ulonglong2*)&row2[0][p];
            ulonglong2 r_1 = *(const ulonglong2*)&row2[1][p];
            ulonglong2 r_2 = *(const ulonglong2*)&row2[2][p];
            ulonglong2 r_3 = *(const ulonglong2*)&row2[3][p];
            fma2(a0, r_0.x, w0); fma2(a0, r_0.y, w1);
            fma2(a1, r_1.x, w0); fma2(a1, r_1.y, w1);
            fma2(a2, r_2.x, w0); fma2(a2, r_2.y, w1);
            fma2(a3, r_3.x, w0); fma2(a3, r_3.y, w1);
        }
        float acc[4] = { hadd(a0), hadd(a1), hadd(a2), hadd(a3) };
        if (qtr > 0) {
            #pragma unroll
            for (int ro = 0; ro < 4; ro++) partial[qtr - 1][ro][jc] = acc[ro];
        }
        __syncthreads();
        if (qtr == 0) {
            #pragma unroll
            for (int ro = 0; ro < 4; ro++) {
                float z = acc[ro] + partial[0][ro][jc] + partial[1][ro][jc] + partial[2][ro][jc]
                        + bks[jc] + qb[jc];
                float v = Wej * tanhapx(z);
                #pragma unroll
                for (int o = 16; o > 0; o >>= 1) v += __shfl_down_sync(0xffffffffu, v, o);
                if ((jc & 31) == 0) part2[ro][jc >> 5] = v;
            }
        }
        __syncthreads();
        if (tid < 4) {
            float e = part2[tid][0] + part2[tid][1] + part2[tid][2] + part2[tid][3] + bev;
            int r2 = r0 + rr + tid;
            int tt = r2 & 511;
            float m = g_mask[tt * Bsz + b];
            g_energy[r2] = e - (1.f - m) * 1e9f;
        }
        __syncthreads();
    }
}

// ================= K5: softmax over t + context =============================
__global__ __launch_bounds__(256, 1)
void k_softctx(float* __restrict__ out) {
    __shared__ float wsm[512];
    __shared__ float red[256];
    int b = blockIdx.x, tid = threadIdx.x;
    float e0 = g_energy[(size_t)b * 512 + tid];
    float e1 = g_energy[(size_t)b * 512 + 256 + tid];
    red[tid] = fmaxf(e0, e1);
    __syncthreads();
    #pragma unroll
    for (int o = 128; o > 0; o >>= 1) {
        if (tid < o) red[tid] = fmaxf(red[tid], red[tid + o]);
        __syncthreads();
    }
    float mx = red[0];
    __syncthreads();
    float x0 = __expf(e0 - mx), x1 = __expf(e1 - mx);
    wsm[tid] = x0; wsm[256 + tid] = x1;
    red[tid] = x0 + x1;
    __syncthreads();
    #pragma unroll
    for (int o = 128; o > 0; o >>= 1) {
        if (tid < o) red[tid] += red[tid + o];
        __syncthreads();
    }
    float inv = __fdividef(1.f, red[0]);

    const float* ob = g_out + (size_t)b * 512 * 256;
    float acc = 0.f;
    #pragma unroll 4
    for (int t = 0; t < 512; t++)
        acc = fmaf(wsm[t], __ldg(ob + (size_t)t * 256 + tid), acc);
    out[(size_t)b * 256 + tid] = acc * inv;
}

// ================= launch ===================================================
extern "C" void kernel_launch(void* const* d_in, const int* in_sizes, int n_in,
                              void* d_out, int out_size) {
    const int*   tags  = (const int*)  d_in[0];
    const float* skips = (const float*)d_in[1];
    const float* emb   = (const float*)d_in[2];
    const float* Kf    = (const float*)d_in[3];
    const float* Rf    = (const float*)d_in[4];
    const float* Skf   = (const float*)d_in[5];
    const float* bf    = (const float*)d_in[6];
    const float* Kb    = (const float*)d_in[7];
    const float* Rb    = (const float*)d_in[8];
    const float* Skb   = (const float*)d_in[9];
    const float* bb    = (const float*)d_in[10];
    const float* Wk    = (const float*)d_in[11];
    const float* bk    = (const float*)d_in[12];
    const float* Wq    = (const float*)d_in[13];
    const float* bq    = (const float*)d_in[14];
    const float* We    = (const float*)d_in[15];
    const float* be    = (const float*)d_in[16];
    float* out = (float*)d_out;

    cudaFuncSetAttribute(k_lstm, cudaFuncAttributeMaxDynamicSharedMemorySize, LSTM_SMEM);
    cudaFuncSetAttribute(k_progemm, cudaFuncAttributeMaxDynamicSharedMemorySize, PSM_TOTAL);

    k_embed<<<NROWS / 8, 256>>>(tags, emb);
    k_progemm<<<dim3(64, 2), 512, PSM_TOTAL>>>(skips, Kf, Skf, Kb, Skb);
    k_lstm<<<dim3(64, 2), 256, LSTM_SMEM>>>(Rf, Rb, bf, bb);
    k_keys<<<1024, 512>>>(Wk, bk, Wq, bq, We, be);   // launch #4 -> ncu
    k_softctx<<<Bsz, 256>>>(out);
}